// round 9
// baseline (speedup 1.0000x reference)
#include <cuda_runtime.h>

#define NN 50000
#define TT 10
#define EE 1000000
#define HH 8

// ---------------- device scratch (no allocations allowed) ----------------
__device__ float g_hidden[NN * HH];   // [N,H] hidden state
__device__ float g_s[NN];             // per-node sigmoid(message MLP)
__device__ float g_agg[NN];           // per-node aggregated messages
__device__ float g_eaT[TT * EE];      // edge_attr transposed to [T,E]
__device__ float g_x0T[TT * NN];      // x[:,t,0] transposed to [T,N]
__device__ float g_x1T[TT * NN];      // x[:,t,1] transposed to [T,N]

// ---------------- weights in shared memory ----------------
struct __align__(16) Weights {
    float m1w1[9 * 32];
    float m1b1[32];
    float m1w2[32 * 32];
    float m1b2[32];
    float m1w3[32];
    float m1b3;
    float pad[3];
    float m2w1[10 * 32];
    float m2b1[32];
    float m2w2[32 * 8];
    float m2b2[8];
    float ow1[8 * 16];
    float ob1[16];
    float ow2[16];
    float ob2;
};

struct WPtrs {
    const float *m1w1, *m1b1, *m1w2, *m1b2, *m1w3, *m1b3;
    const float *m2w1, *m2b1, *m2w2, *m2b2;
    const float *ow1, *ob1, *ow2, *ob2;
};

__device__ __forceinline__ void load_weights(Weights* W, const WPtrs p) {
    const int tid = threadIdx.x, nt = blockDim.x;
    for (int i = tid; i < 9 * 32; i += nt)  W->m1w1[i] = p.m1w1[i];
    for (int i = tid; i < 32; i += nt)      W->m1b1[i] = p.m1b1[i];
    for (int i = tid; i < 32 * 32; i += nt) W->m1w2[i] = p.m1w2[i];
    for (int i = tid; i < 32; i += nt)      W->m1b2[i] = p.m1b2[i];
    for (int i = tid; i < 32; i += nt)      W->m1w3[i] = p.m1w3[i];
    for (int i = tid; i < 10 * 32; i += nt) W->m2w1[i] = p.m2w1[i];
    for (int i = tid; i < 32; i += nt)      W->m2b1[i] = p.m2b1[i];
    for (int i = tid; i < 32 * 8; i += nt)  W->m2w2[i] = p.m2w2[i];
    for (int i = tid; i < 8; i += nt)       W->m2b2[i] = p.m2b2[i];
    for (int i = tid; i < 8 * 16; i += nt)  W->ow1[i] = p.ow1[i];
    for (int i = tid; i < 16; i += nt)      W->ob1[i] = p.ob1[i];
    for (int i = tid; i < 16; i += nt)      W->ow2[i] = p.ow2[i];
    if (tid == 0) { W->m1b3 = p.m1b3[0]; W->ob2 = p.ob2[0]; }
}

// ---------------- branch-free fast activations ----------------
__device__ __forceinline__ float rcp_approx(float x) {
    float r; asm("rcp.approx.f32 %0, %1;" : "=f"(r) : "f"(x)); return r;
}
__device__ __forceinline__ float fast_sigmoid(float z) {
    return rcp_approx(1.0f + __expf(-z));
}
// tanh for x >= 0 (post-ReLU): tanh(x) = 1 - 2/(e^{2x}+1), branch-free.
__device__ __forceinline__ float fast_tanh_nonneg(float x) {
    x = fminf(x, 15.0f);
    float e = __expf(2.0f * x);
    return fmaf(-2.0f, rcp_approx(e + 1.0f), 1.0f);
}

// ===================== low-register scalar MLPs (1 node per lane) =====================

// Message MLP [x0, h(8)] -> 32 -> relu -> 32 -> relu -> 1 -> sigmoid
// Layer 2+3 are computed in TWO sequential 16-wide passes so that the live set
// stays at a[32]+b[16] (~48 floats) instead of a[32]+b[32] -> no register spills.
__device__ __forceinline__ float mlp1(const Weights* W, float x0, const float h[HH]) {
    float a[32];
    {
        const float4* wv = (const float4*)W->m1w1;
        const float4* bv = (const float4*)W->m1b1;
        #pragma unroll
        for (int j4 = 0; j4 < 8; j4++) {
            float4 w = wv[j4]; float4 b = bv[j4];
            a[4*j4+0] = fmaf(x0, w.x, b.x);
            a[4*j4+1] = fmaf(x0, w.y, b.y);
            a[4*j4+2] = fmaf(x0, w.z, b.z);
            a[4*j4+3] = fmaf(x0, w.w, b.w);
        }
    }
    #pragma unroll
    for (int i = 0; i < HH; i++) {
        float hi = h[i];
        const float4* wr = (const float4*)(W->m1w1 + (i + 1) * 32);
        #pragma unroll
        for (int j4 = 0; j4 < 8; j4++) {
            float4 w = wr[j4];
            a[4*j4+0] = fmaf(hi, w.x, a[4*j4+0]);
            a[4*j4+1] = fmaf(hi, w.y, a[4*j4+1]);
            a[4*j4+2] = fmaf(hi, w.z, a[4*j4+2]);
            a[4*j4+3] = fmaf(hi, w.w, a[4*j4+3]);
        }
    }
    #pragma unroll
    for (int j = 0; j < 32; j++) a[j] = fmaxf(a[j], 0.0f);

    float z = W->m1b3;
    #pragma unroll 1
    for (int half = 0; half < 2; half++) {
        const int off = half * 16;
        float b[16];
        {
            const float4* bv = (const float4*)(W->m1b2 + off);
            #pragma unroll
            for (int j4 = 0; j4 < 4; j4++) {
                float4 bb = bv[j4];
                b[4*j4+0]=bb.x; b[4*j4+1]=bb.y; b[4*j4+2]=bb.z; b[4*j4+3]=bb.w;
            }
        }
        #pragma unroll
        for (int i = 0; i < 32; i++) {
            float ai = a[i];
            const float4* wr = (const float4*)(W->m1w2 + i * 32 + off);
            #pragma unroll
            for (int j4 = 0; j4 < 4; j4++) {
                float4 w = wr[j4];
                b[4*j4+0] = fmaf(ai, w.x, b[4*j4+0]);
                b[4*j4+1] = fmaf(ai, w.y, b[4*j4+1]);
                b[4*j4+2] = fmaf(ai, w.z, b[4*j4+2]);
                b[4*j4+3] = fmaf(ai, w.w, b[4*j4+3]);
            }
        }
        const float4* wv = (const float4*)(W->m1w3 + off);
        #pragma unroll
        for (int i4 = 0; i4 < 4; i4++) {
            float4 w = wv[i4];
            z = fmaf(fmaxf(b[4*i4+0], 0.0f), w.x, z);
            z = fmaf(fmaxf(b[4*i4+1], 0.0f), w.y, z);
            z = fmaf(fmaxf(b[4*i4+2], 0.0f), w.z, z);
            z = fmaf(fmaxf(b[4*i4+3], 0.0f), w.w, z);
        }
    }
    return fast_sigmoid(z);
}

// Update MLP [x1,h(8),agg](10) -> 32 -> relu -> 8 -> relu -> tanh  (live: 32+8, OK)
__device__ __forceinline__ void mlp2(const Weights* W, const float upd[10], float hnew[HH]) {
    float a[32];
    {
        const float4* bv = (const float4*)W->m2b1;
        #pragma unroll
        for (int j4 = 0; j4 < 8; j4++) {
            float4 bb = bv[j4];
            a[4*j4+0]=bb.x; a[4*j4+1]=bb.y; a[4*j4+2]=bb.z; a[4*j4+3]=bb.w;
        }
    }
    #pragma unroll
    for (int i = 0; i < 10; i++) {
        float ui = upd[i];
        const float4* wr = (const float4*)(W->m2w1 + i * 32);
        #pragma unroll
        for (int j4 = 0; j4 < 8; j4++) {
            float4 w = wr[j4];
            a[4*j4+0] = fmaf(ui, w.x, a[4*j4+0]);
            a[4*j4+1] = fmaf(ui, w.y, a[4*j4+1]);
            a[4*j4+2] = fmaf(ui, w.z, a[4*j4+2]);
            a[4*j4+3] = fmaf(ui, w.w, a[4*j4+3]);
        }
    }
    #pragma unroll
    for (int j = 0; j < 32; j++) a[j] = fmaxf(a[j], 0.0f);

    float b[HH];
    {
        const float4* bv = (const float4*)W->m2b2;
        float4 b0 = bv[0], b1 = bv[1];
        b[0]=b0.x; b[1]=b0.y; b[2]=b0.z; b[3]=b0.w;
        b[4]=b1.x; b[5]=b1.y; b[6]=b1.z; b[7]=b1.w;
    }
    #pragma unroll
    for (int i = 0; i < 32; i++) {
        float ai = a[i];
        const float4* wr = (const float4*)(W->m2w2 + i * 8);
        float4 w0 = wr[0], w1 = wr[1];
        b[0]=fmaf(ai,w0.x,b[0]); b[1]=fmaf(ai,w0.y,b[1]);
        b[2]=fmaf(ai,w0.z,b[2]); b[3]=fmaf(ai,w0.w,b[3]);
        b[4]=fmaf(ai,w1.x,b[4]); b[5]=fmaf(ai,w1.y,b[5]);
        b[6]=fmaf(ai,w1.z,b[6]); b[7]=fmaf(ai,w1.w,b[7]);
    }
    // hidden_new = tanh(relu(z2))
    #pragma unroll
    for (int j = 0; j < HH; j++) hnew[j] = fast_tanh_nonneg(fmaxf(b[j], 0.0f));
}

// Readout hidden(8) -> 16 -> relu -> 1 -> sigmoid  (live: 16+8, OK)
__device__ __forceinline__ float node_out(const Weights* W, const float hnew[HH]) {
    float o[16];
    {
        const float4* bv = (const float4*)W->ob1;
        #pragma unroll
        for (int j4 = 0; j4 < 4; j4++) {
            float4 bb = bv[j4];
            o[4*j4+0]=bb.x; o[4*j4+1]=bb.y; o[4*j4+2]=bb.z; o[4*j4+3]=bb.w;
        }
    }
    #pragma unroll
    for (int i = 0; i < HH; i++) {
        float hi = hnew[i];
        const float4* wr = (const float4*)(W->ow1 + i * 16);
        #pragma unroll
        for (int j4 = 0; j4 < 4; j4++) {
            float4 w = wr[j4];
            o[4*j4+0]=fmaf(hi,w.x,o[4*j4+0]); o[4*j4+1]=fmaf(hi,w.y,o[4*j4+1]);
            o[4*j4+2]=fmaf(hi,w.z,o[4*j4+2]); o[4*j4+3]=fmaf(hi,w.w,o[4*j4+3]);
        }
    }
    float z = W->ob2;
    {
        const float4* wv = (const float4*)W->ow2;
        #pragma unroll
        for (int i4 = 0; i4 < 4; i4++) {
            float4 w = wv[i4];
            z = fmaf(fmaxf(o[4*i4+0],0.f), w.x, z);
            z = fmaf(fmaxf(o[4*i4+1],0.f), w.y, z);
            z = fmaf(fmaxf(o[4*i4+2],0.f), w.z, z);
            z = fmaf(fmaxf(o[4*i4+3],0.f), w.w, z);
        }
    }
    return fast_sigmoid(z);
}

// ---------------- kernels ----------------

// One-time transposes: edge_attr [E,T,1]->[T,E]; x [N,T,2]->[T,N] per channel.
__global__ void transpose_ea_kernel(const float* __restrict__ ea) {
    int e = blockIdx.x * blockDim.x + threadIdx.x;
    if (e >= EE) return;
    #pragma unroll
    for (int t = 0; t < TT; t++) g_eaT[t * EE + e] = ea[e * TT + t];
}

__global__ void transpose_x_kernel(const float* __restrict__ x) {
    int n = blockIdx.x * blockDim.x + threadIdx.x;
    if (n >= NN) return;
    #pragma unroll
    for (int t = 0; t < TT; t++) {
        float2 v = ((const float2*)x)[n * TT + t];
        g_x0T[t * NN + n] = v.x;
        g_x1T[t * NN + n] = v.y;
    }
}

// Frame 0 prologue: hidden = 0, agg = 0, s = sigmoid(MLP1([x0, 0]))
__global__ void __launch_bounds__(256) prologue_kernel(const WPtrs p) {
    __shared__ Weights W;
    load_weights(&W, p);
    __syncthreads();
    int n = blockIdx.x * blockDim.x + threadIdx.x;
    if (n >= NN) return;
    float h0[HH] = {0.f,0.f,0.f,0.f,0.f,0.f,0.f,0.f};
    float x0 = g_x0T[n];
    g_s[n] = mlp1(&W, x0, h0);
    g_agg[n] = 0.0f;
    float4 z4 = make_float4(0.f, 0.f, 0.f, 0.f);
    ((float4*)g_hidden)[n * 2 + 0] = z4;
    ((float4*)g_hidden)[n * 2 + 1] = z4;
}

// Per-frame edge scatter: agg[dst] += s[src] * ea ; 4 edges per thread.
__global__ void edge_kernel(const int* __restrict__ ei, int t) {
    int e4 = blockIdx.x * blockDim.x + threadIdx.x;
    if (e4 >= EE / 4) return;
    int4 s4 = ((const int4*)(ei + t * EE))[e4];
    int4 d4 = ((const int4*)(ei + (TT + t) * EE))[e4];
    float4 a4 = ((const float4*)(g_eaT + t * EE))[e4];
    atomicAdd(&g_agg[d4.x], __ldg(&g_s[s4.x]) * a4.x);
    atomicAdd(&g_agg[d4.y], __ldg(&g_s[s4.y]) * a4.y);
    atomicAdd(&g_agg[d4.z], __ldg(&g_s[s4.z]) * a4.z);
    atomicAdd(&g_agg[d4.w], __ldg(&g_s[s4.w]) * a4.w);
}

// Per-frame node update (+ fused message-MLP for next frame), 1 node/lane.
__global__ void __launch_bounds__(256) update_kernel(float* __restrict__ out,
                                                     const WPtrs p, int t) {
    __shared__ Weights W;
    load_weights(&W, p);
    __syncthreads();
    int n = blockIdx.x * blockDim.x + threadIdx.x;
    if (n >= NN) return;

    float4 h0 = ((const float4*)g_hidden)[n * 2 + 0];
    float4 h1 = ((const float4*)g_hidden)[n * 2 + 1];

    float upd[10];
    upd[0] = g_x1T[t * NN + n];
    upd[1]=h0.x; upd[2]=h0.y; upd[3]=h0.z; upd[4]=h0.w;
    upd[5]=h1.x; upd[6]=h1.y; upd[7]=h1.z; upd[8]=h1.w;
    upd[9] = g_agg[n];   // AGG_MEAN=0, AGG_VAR=1 -> identity norm

    float hn[HH];
    mlp2(&W, upd, hn);

    ((float4*)g_hidden)[n * 2 + 0] = make_float4(hn[0], hn[1], hn[2], hn[3]);
    ((float4*)g_hidden)[n * 2 + 1] = make_float4(hn[4], hn[5], hn[6], hn[7]);

    out[t * NN + n] = node_out(&W, hn);

    if (t < TT - 1) {
        float x0n = g_x0T[(t + 1) * NN + n];
        g_s[n] = mlp1(&W, x0n, hn);
        g_agg[n] = 0.0f;
    }
}

// ---------------- launch ----------------
extern "C" void kernel_launch(void* const* d_in, const int* in_sizes, int n_in,
                              void* d_out, int out_size) {
    const float* x  = (const float*)d_in[0];
    const int*   ei = (const int*)d_in[1];
    const float* ea = (const float*)d_in[2];
    WPtrs p;
    p.m1w1 = (const float*)d_in[3];  p.m1b1 = (const float*)d_in[4];
    p.m1w2 = (const float*)d_in[5];  p.m1b2 = (const float*)d_in[6];
    p.m1w3 = (const float*)d_in[7];  p.m1b3 = (const float*)d_in[8];
    p.m2w1 = (const float*)d_in[9];  p.m2b1 = (const float*)d_in[10];
    p.m2w2 = (const float*)d_in[11]; p.m2b2 = (const float*)d_in[12];
    p.ow1  = (const float*)d_in[13]; p.ob1  = (const float*)d_in[14];
    p.ow2  = (const float*)d_in[15]; p.ob2  = (const float*)d_in[16];
    float* out = (float*)d_out;

    const int NODE_GRID = 296;   // 2 * 148 SMs, 256 threads: 75776 >= 50000

    transpose_ea_kernel<<<(EE + 255) / 256, 256>>>(ea);
    transpose_x_kernel<<<(NN + 255) / 256, 256>>>(x);
    prologue_kernel<<<NODE_GRID, 256>>>(p);
    for (int t = 0; t < TT; t++) {
        edge_kernel<<<(EE / 4 + 255) / 256, 256>>>(ei, t);
        update_kernel<<<NODE_GRID, 256>>>(out, p, t);
    }
}

// round 10
// speedup vs baseline: 1.2320x; 1.2320x over previous
#include <cuda_runtime.h>

#define NN 50000
#define TT 10
#define EE 1000000
#define HH 8

// ---------------- device scratch (no allocations allowed) ----------------
__device__ float g_hidden[NN * HH];   // [N,H] hidden state
__device__ float g_s[NN];             // per-node sigmoid(message MLP)
__device__ float g_agg[NN];           // per-node aggregated messages
__device__ float g_eaT[TT * EE];      // edge_attr transposed to [T,E]
__device__ float g_x0T[TT * NN];      // x[:,t,0] transposed to [T,N]
__device__ float g_x1T[TT * NN];      // x[:,t,1] transposed to [T,N]

// ---------------- weights: packed staging + constant bank ----------------
struct __align__(16) Weights {
    float m1w1[9 * 32];    // @0
    float m1b1[32];        // @288
    float m1w2[32 * 32];   // @320
    float m1b2[32];        // @1344
    float m1w3[32];        // @1376
    float m1b3;            // @1408
    float pad[3];
    float m2w1[10 * 32];   // @1412
    float m2b1[32];        // @1732
    float m2w2[32 * 8];    // @1764
    float m2b2[8];         // @2020
    float ow1[8 * 16];     // @2028
    float ob1[16];         // @2156
    float ow2[16];         // @2172
    float ob2;             // @2188
    float pad2[3];         // -> 2192 floats total
};

__device__   Weights g_wstage;   // staging, written by pack kernel
__constant__ Weights cW;         // read by all MLP kernels

struct WPtrs {
    const float *m1w1, *m1b1, *m1w2, *m1b2, *m1w3, *m1b3;
    const float *m2w1, *m2b1, *m2w2, *m2b2;
    const float *ow1, *ob1, *ow2, *ob2;
};

__global__ void pack_weights_kernel(const WPtrs p) {
    const int tid = threadIdx.x, nt = blockDim.x;
    for (int i = tid; i < 9 * 32; i += nt)  g_wstage.m1w1[i] = p.m1w1[i];
    for (int i = tid; i < 32; i += nt)      g_wstage.m1b1[i] = p.m1b1[i];
    for (int i = tid; i < 32 * 32; i += nt) g_wstage.m1w2[i] = p.m1w2[i];
    for (int i = tid; i < 32; i += nt)      g_wstage.m1b2[i] = p.m1b2[i];
    for (int i = tid; i < 32; i += nt)      g_wstage.m1w3[i] = p.m1w3[i];
    for (int i = tid; i < 10 * 32; i += nt) g_wstage.m2w1[i] = p.m2w1[i];
    for (int i = tid; i < 32; i += nt)      g_wstage.m2b1[i] = p.m2b1[i];
    for (int i = tid; i < 32 * 8; i += nt)  g_wstage.m2w2[i] = p.m2w2[i];
    for (int i = tid; i < 8; i += nt)       g_wstage.m2b2[i] = p.m2b2[i];
    for (int i = tid; i < 8 * 16; i += nt)  g_wstage.ow1[i] = p.ow1[i];
    for (int i = tid; i < 16; i += nt)      g_wstage.ob1[i] = p.ob1[i];
    for (int i = tid; i < 16; i += nt)      g_wstage.ow2[i] = p.ow2[i];
    if (tid == 0) { g_wstage.m1b3 = p.m1b3[0]; g_wstage.ob2 = p.ob2[0]; }
}

// ---------------- branch-free fast activations ----------------
__device__ __forceinline__ float rcp_approx(float x) {
    float r; asm("rcp.approx.f32 %0, %1;" : "=f"(r) : "f"(x)); return r;
}
__device__ __forceinline__ float fast_sigmoid(float z) {
    return rcp_approx(1.0f + __expf(-z));
}
// tanh for x >= 0 (post-ReLU): tanh(x) = 1 - 2/(e^{2x}+1), branch-free.
__device__ __forceinline__ float fast_tanh_nonneg(float x) {
    x = fminf(x, 15.0f);
    float e = __expf(2.0f * x);
    return fmaf(-2.0f, rcp_approx(e + 1.0f), 1.0f);
}

// ===================== scalar MLPs, weights from __constant__ =====================

// Message MLP [x0, h(8)] -> 32 -> relu -> 32 -> relu -> 1 -> sigmoid
__device__ __forceinline__ float mlp1(float x0, const float h[HH]) {
    float a[32];
    {
        const float4* wv = (const float4*)cW.m1w1;
        const float4* bv = (const float4*)cW.m1b1;
        #pragma unroll
        for (int j4 = 0; j4 < 8; j4++) {
            float4 w = wv[j4]; float4 b = bv[j4];
            a[4*j4+0] = fmaf(x0, w.x, b.x);
            a[4*j4+1] = fmaf(x0, w.y, b.y);
            a[4*j4+2] = fmaf(x0, w.z, b.z);
            a[4*j4+3] = fmaf(x0, w.w, b.w);
        }
    }
    #pragma unroll
    for (int i = 0; i < HH; i++) {
        float hi = h[i];
        const float4* wr = (const float4*)(cW.m1w1 + (i + 1) * 32);
        #pragma unroll
        for (int j4 = 0; j4 < 8; j4++) {
            float4 w = wr[j4];
            a[4*j4+0] = fmaf(hi, w.x, a[4*j4+0]);
            a[4*j4+1] = fmaf(hi, w.y, a[4*j4+1]);
            a[4*j4+2] = fmaf(hi, w.z, a[4*j4+2]);
            a[4*j4+3] = fmaf(hi, w.w, a[4*j4+3]);
        }
    }
    #pragma unroll
    for (int j = 0; j < 32; j++) a[j] = fmaxf(a[j], 0.0f);

    float b[32];
    {
        const float4* bv = (const float4*)cW.m1b2;
        #pragma unroll
        for (int j4 = 0; j4 < 8; j4++) {
            float4 bb = bv[j4];
            b[4*j4+0]=bb.x; b[4*j4+1]=bb.y; b[4*j4+2]=bb.z; b[4*j4+3]=bb.w;
        }
    }
    #pragma unroll
    for (int i = 0; i < 32; i++) {
        float ai = a[i];
        const float4* wr = (const float4*)(cW.m1w2 + i * 32);
        #pragma unroll
        for (int j4 = 0; j4 < 8; j4++) {
            float4 w = wr[j4];
            b[4*j4+0] = fmaf(ai, w.x, b[4*j4+0]);
            b[4*j4+1] = fmaf(ai, w.y, b[4*j4+1]);
            b[4*j4+2] = fmaf(ai, w.z, b[4*j4+2]);
            b[4*j4+3] = fmaf(ai, w.w, b[4*j4+3]);
        }
    }
    float z = cW.m1b3;
    {
        const float4* wv = (const float4*)cW.m1w3;
        #pragma unroll
        for (int i4 = 0; i4 < 8; i4++) {
            float4 w = wv[i4];
            z = fmaf(fmaxf(b[4*i4+0], 0.0f), w.x, z);
            z = fmaf(fmaxf(b[4*i4+1], 0.0f), w.y, z);
            z = fmaf(fmaxf(b[4*i4+2], 0.0f), w.z, z);
            z = fmaf(fmaxf(b[4*i4+3], 0.0f), w.w, z);
        }
    }
    return fast_sigmoid(z);
}

// Update MLP [x1,h(8),agg](10) -> 32 -> relu -> 8 -> relu -> tanh
__device__ __forceinline__ void mlp2(const float upd[10], float hnew[HH]) {
    float a[32];
    {
        const float4* bv = (const float4*)cW.m2b1;
        #pragma unroll
        for (int j4 = 0; j4 < 8; j4++) {
            float4 bb = bv[j4];
            a[4*j4+0]=bb.x; a[4*j4+1]=bb.y; a[4*j4+2]=bb.z; a[4*j4+3]=bb.w;
        }
    }
    #pragma unroll
    for (int i = 0; i < 10; i++) {
        float ui = upd[i];
        const float4* wr = (const float4*)(cW.m2w1 + i * 32);
        #pragma unroll
        for (int j4 = 0; j4 < 8; j4++) {
            float4 w = wr[j4];
            a[4*j4+0] = fmaf(ui, w.x, a[4*j4+0]);
            a[4*j4+1] = fmaf(ui, w.y, a[4*j4+1]);
            a[4*j4+2] = fmaf(ui, w.z, a[4*j4+2]);
            a[4*j4+3] = fmaf(ui, w.w, a[4*j4+3]);
        }
    }
    #pragma unroll
    for (int j = 0; j < 32; j++) a[j] = fmaxf(a[j], 0.0f);

    float b[HH];
    {
        const float4* bv = (const float4*)cW.m2b2;
        float4 b0 = bv[0], b1 = bv[1];
        b[0]=b0.x; b[1]=b0.y; b[2]=b0.z; b[3]=b0.w;
        b[4]=b1.x; b[5]=b1.y; b[6]=b1.z; b[7]=b1.w;
    }
    #pragma unroll
    for (int i = 0; i < 32; i++) {
        float ai = a[i];
        const float4* wr = (const float4*)(cW.m2w2 + i * 8);
        float4 w0 = wr[0], w1 = wr[1];
        b[0]=fmaf(ai,w0.x,b[0]); b[1]=fmaf(ai,w0.y,b[1]);
        b[2]=fmaf(ai,w0.z,b[2]); b[3]=fmaf(ai,w0.w,b[3]);
        b[4]=fmaf(ai,w1.x,b[4]); b[5]=fmaf(ai,w1.y,b[5]);
        b[6]=fmaf(ai,w1.z,b[6]); b[7]=fmaf(ai,w1.w,b[7]);
    }
    // hidden_new = tanh(relu(z2))
    #pragma unroll
    for (int j = 0; j < HH; j++) hnew[j] = fast_tanh_nonneg(fmaxf(b[j], 0.0f));
}

// Readout hidden(8) -> 16 -> relu -> 1 -> sigmoid
__device__ __forceinline__ float node_out(const float hnew[HH]) {
    float o[16];
    {
        const float4* bv = (const float4*)cW.ob1;
        #pragma unroll
        for (int j4 = 0; j4 < 4; j4++) {
            float4 bb = bv[j4];
            o[4*j4+0]=bb.x; o[4*j4+1]=bb.y; o[4*j4+2]=bb.z; o[4*j4+3]=bb.w;
        }
    }
    #pragma unroll
    for (int i = 0; i < HH; i++) {
        float hi = hnew[i];
        const float4* wr = (const float4*)(cW.ow1 + i * 16);
        #pragma unroll
        for (int j4 = 0; j4 < 4; j4++) {
            float4 w = wr[j4];
            o[4*j4+0]=fmaf(hi,w.x,o[4*j4+0]); o[4*j4+1]=fmaf(hi,w.y,o[4*j4+1]);
            o[4*j4+2]=fmaf(hi,w.z,o[4*j4+2]); o[4*j4+3]=fmaf(hi,w.w,o[4*j4+3]);
        }
    }
    float z = cW.ob2;
    {
        const float4* wv = (const float4*)cW.ow2;
        #pragma unroll
        for (int i4 = 0; i4 < 4; i4++) {
            float4 w = wv[i4];
            z = fmaf(fmaxf(o[4*i4+0],0.f), w.x, z);
            z = fmaf(fmaxf(o[4*i4+1],0.f), w.y, z);
            z = fmaf(fmaxf(o[4*i4+2],0.f), w.z, z);
            z = fmaf(fmaxf(o[4*i4+3],0.f), w.w, z);
        }
    }
    return fast_sigmoid(z);
}

// ---------------- kernels ----------------

// One-time transposes, fused: edge_attr [E,T,1]->[T,E] and x [N,T,2]->[T,N]x2.
__global__ void transpose_kernel(const float* __restrict__ ea,
                                 const float* __restrict__ x) {
    int e = blockIdx.x * blockDim.x + threadIdx.x;
    if (e < EE) {
        #pragma unroll
        for (int t = 0; t < TT; t++) g_eaT[t * EE + e] = ea[e * TT + t];
    }
    if (e < NN) {
        #pragma unroll
        for (int t = 0; t < TT; t++) {
            float2 v = ((const float2*)x)[e * TT + t];
            g_x0T[t * NN + e] = v.x;
            g_x1T[t * NN + e] = v.y;
        }
    }
}

// Frame 0 prologue: hidden = 0, agg = 0, s = sigmoid(MLP1([x0, 0]))
__global__ void __launch_bounds__(128) prologue_kernel() {
    int n = blockIdx.x * blockDim.x + threadIdx.x;
    if (n >= NN) return;
    float h0[HH] = {0.f,0.f,0.f,0.f,0.f,0.f,0.f,0.f};
    float x0 = g_x0T[n];
    g_s[n] = mlp1(x0, h0);
    g_agg[n] = 0.0f;
    float4 z4 = make_float4(0.f, 0.f, 0.f, 0.f);
    ((float4*)g_hidden)[n * 2 + 0] = z4;
    ((float4*)g_hidden)[n * 2 + 1] = z4;
}

// Per-frame edge scatter: agg[dst] += s[src] * ea ; 4 edges per thread.
__global__ void edge_kernel(const int* __restrict__ ei, int t) {
    int e4 = blockIdx.x * blockDim.x + threadIdx.x;
    if (e4 >= EE / 4) return;
    int4 s4 = ((const int4*)(ei + t * EE))[e4];
    int4 d4 = ((const int4*)(ei + (TT + t) * EE))[e4];
    float4 a4 = ((const float4*)(g_eaT + t * EE))[e4];
    atomicAdd(&g_agg[d4.x], __ldg(&g_s[s4.x]) * a4.x);
    atomicAdd(&g_agg[d4.y], __ldg(&g_s[s4.y]) * a4.y);
    atomicAdd(&g_agg[d4.z], __ldg(&g_s[s4.z]) * a4.z);
    atomicAdd(&g_agg[d4.w], __ldg(&g_s[s4.w]) * a4.w);
}

// Per-frame node update (+ fused message-MLP for next frame), 1 node/lane.
__global__ void __launch_bounds__(128) update_kernel(float* __restrict__ out, int t) {
    int n = blockIdx.x * blockDim.x + threadIdx.x;
    if (n >= NN) return;

    float4 h0 = ((const float4*)g_hidden)[n * 2 + 0];
    float4 h1 = ((const float4*)g_hidden)[n * 2 + 1];

    float upd[10];
    upd[0] = g_x1T[t * NN + n];
    upd[1]=h0.x; upd[2]=h0.y; upd[3]=h0.z; upd[4]=h0.w;
    upd[5]=h1.x; upd[6]=h1.y; upd[7]=h1.z; upd[8]=h1.w;
    upd[9] = g_agg[n];   // AGG_MEAN=0, AGG_VAR=1 -> identity norm

    float hn[HH];
    mlp2(upd, hn);

    ((float4*)g_hidden)[n * 2 + 0] = make_float4(hn[0], hn[1], hn[2], hn[3]);
    ((float4*)g_hidden)[n * 2 + 1] = make_float4(hn[4], hn[5], hn[6], hn[7]);

    out[t * NN + n] = node_out(hn);

    if (t < TT - 1) {
        float x0n = g_x0T[(t + 1) * NN + n];
        g_s[n] = mlp1(x0n, hn);
        g_agg[n] = 0.0f;
    }
}

// ---------------- launch ----------------
extern "C" void kernel_launch(void* const* d_in, const int* in_sizes, int n_in,
                              void* d_out, int out_size) {
    const float* x  = (const float*)d_in[0];
    const int*   ei = (const int*)d_in[1];
    const float* ea = (const float*)d_in[2];
    WPtrs p;
    p.m1w1 = (const float*)d_in[3];  p.m1b1 = (const float*)d_in[4];
    p.m1w2 = (const float*)d_in[5];  p.m1b2 = (const float*)d_in[6];
    p.m1w3 = (const float*)d_in[7];  p.m1b3 = (const float*)d_in[8];
    p.m2w1 = (const float*)d_in[9];  p.m2b1 = (const float*)d_in[10];
    p.m2w2 = (const float*)d_in[11]; p.m2b2 = (const float*)d_in[12];
    p.ow1  = (const float*)d_in[13]; p.ob1  = (const float*)d_in[14];
    p.ow2  = (const float*)d_in[15]; p.ob2  = (const float*)d_in[16];
    float* out = (float*)d_out;

    // Stage weights in device memory, then copy into the constant bank.
    // (cudaGetSymbolAddress is a host-side query; the copy is a D2D memcpy
    //  node — both graph-capture legal. No allocations anywhere.)
    pack_weights_kernel<<<1, 256>>>(p);
    void* cw_addr = nullptr;
    void* st_addr = nullptr;
    cudaGetSymbolAddress(&cw_addr, cW);
    cudaGetSymbolAddress(&st_addr, g_wstage);
    cudaMemcpyAsync(cw_addr, st_addr, sizeof(Weights), cudaMemcpyDeviceToDevice, 0);

    transpose_kernel<<<(EE + 255) / 256, 256>>>(ea, x);
    prologue_kernel<<<(NN + 127) / 128, 128>>>();
    for (int t = 0; t < TT; t++) {
        edge_kernel<<<(EE / 4 + 255) / 256, 256>>>(ei, t);
        update_kernel<<<(NN + 127) / 128, 128>>>(out, t);
    }
}

// round 12
// speedup vs baseline: 1.2357x; 1.0031x over previous
#include <cuda_runtime.h>

#define NN 50000
#define TT 10
#define EE 1000000
#define HH 8

typedef unsigned long long u64;

// ---------------- device scratch (no allocations allowed) ----------------
__device__ float g_hidden[NN * HH];   // [N,H] hidden state
__device__ float g_s[NN];             // per-node sigmoid(message MLP)
__device__ float g_agg[NN];           // per-node aggregated messages
__device__ float g_eaT[TT * EE];      // edge_attr transposed to [T,E]
__device__ float g_x0T[TT * NN];      // x[:,t,0] transposed to [T,N]
__device__ float g_x1T[TT * NN];      // x[:,t,1] transposed to [T,N]

// ---------------- weights: packed staging + constant bank ----------------
struct __align__(16) Weights {
    float m1w1[9 * 32];
    float m1b1[32];
    float m1w2[32 * 32];
    float m1b2[32];
    float m1w3[32];
    float m1b3;
    float pad[3];
    float m2w1[10 * 32];
    float m2b1[32];
    float m2w2[32 * 8];
    float m2b2[8];
    float ow1[8 * 16];
    float ob1[16];
    float ow2[16];
    float ob2;
    float pad2[3];
};

__device__   Weights g_wstage;   // staging, written by pack kernel
__constant__ Weights cW;         // read by all MLP kernels

struct WPtrs {
    const float *m1w1, *m1b1, *m1w2, *m1b2, *m1w3, *m1b3;
    const float *m2w1, *m2b1, *m2w2, *m2b2;
    const float *ow1, *ob1, *ow2, *ob2;
};

__global__ void pack_weights_kernel(const WPtrs p) {
    const int tid = threadIdx.x, nt = blockDim.x;
    for (int i = tid; i < 9 * 32; i += nt)  g_wstage.m1w1[i] = p.m1w1[i];
    for (int i = tid; i < 32; i += nt)      g_wstage.m1b1[i] = p.m1b1[i];
    for (int i = tid; i < 32 * 32; i += nt) g_wstage.m1w2[i] = p.m1w2[i];
    for (int i = tid; i < 32; i += nt)      g_wstage.m1b2[i] = p.m1b2[i];
    for (int i = tid; i < 32; i += nt)      g_wstage.m1w3[i] = p.m1w3[i];
    for (int i = tid; i < 10 * 32; i += nt) g_wstage.m2w1[i] = p.m2w1[i];
    for (int i = tid; i < 32; i += nt)      g_wstage.m2b1[i] = p.m2b1[i];
    for (int i = tid; i < 32 * 8; i += nt)  g_wstage.m2w2[i] = p.m2w2[i];
    for (int i = tid; i < 8; i += nt)       g_wstage.m2b2[i] = p.m2b2[i];
    for (int i = tid; i < 8 * 16; i += nt)  g_wstage.ow1[i] = p.ow1[i];
    for (int i = tid; i < 16; i += nt)      g_wstage.ob1[i] = p.ob1[i];
    for (int i = tid; i < 16; i += nt)      g_wstage.ow2[i] = p.ow2[i];
    if (tid == 0) { g_wstage.m1b3 = p.m1b3[0]; g_wstage.ob2 = p.ob2[0]; }
}

// ---------------- f32x2 packed primitives (Blackwell) ----------------
__device__ __forceinline__ u64 pk2(float lo, float hi) {
    u64 r; asm("mov.b64 %0, {%1,%2};" : "=l"(r) : "f"(lo), "f"(hi)); return r;
}
__device__ __forceinline__ void upk2(u64 v, float& lo, float& hi) {
    asm("mov.b64 {%0,%1}, %2;" : "=f"(lo), "=f"(hi) : "l"(v));
}
__device__ __forceinline__ u64 dup2(float x) { return pk2(x, x); }
__device__ __forceinline__ u64 ffma2(u64 a, u64 b, u64 c) {
    u64 d; asm("fma.rn.f32x2 %0, %1, %2, %3;" : "=l"(d) : "l"(a), "l"(b), "l"(c)); return d;
}
__device__ __forceinline__ u64 relu2(u64 v) {
    float lo, hi; upk2(v, lo, hi);
    return pk2(fmaxf(lo, 0.0f), fmaxf(hi, 0.0f));
}

// ---------------- branch-free fast activations ----------------
__device__ __forceinline__ float rcp_approx(float x) {
    float r; asm("rcp.approx.f32 %0, %1;" : "=f"(r) : "f"(x)); return r;
}
__device__ __forceinline__ float fast_sigmoid(float z) {
    return rcp_approx(1.0f + __expf(-z));
}
// tanh for x >= 0 (post-ReLU): tanh(x) = 1 - 2/(e^{2x}+1), branch-free.
__device__ __forceinline__ float fast_tanh_nonneg(float x) {
    x = fminf(x, 15.0f);
    float e = __expf(2.0f * x);
    return fmaf(-2.0f, rcp_approx(e + 1.0f), 1.0f);
}

// ===================== f32x2 MLPs, weights from __constant__ =====================
// Neuron pairs (2j,2j+1) packed per u64; weight pairs contiguous -> LDCU.128
// yields two packed operands. Inputs broadcast-duplicated.

// Message MLP [x0, h(8)] -> 32 -> relu -> 32 -> relu -> 1 -> sigmoid
__device__ __forceinline__ float mlp1(u64 x0d, const u64 hd[HH]) {
    u64 a2[16];
    {
        const ulonglong2* bv = (const ulonglong2*)cW.m1b1;
        const ulonglong2* wv = (const ulonglong2*)cW.m1w1;   // row 0 (x0)
        #pragma unroll
        for (int j = 0; j < 8; j++) {
            ulonglong2 b = bv[j]; ulonglong2 w = wv[j];
            a2[2*j]   = ffma2(x0d, w.x, b.x);
            a2[2*j+1] = ffma2(x0d, w.y, b.y);
        }
    }
    #pragma unroll
    for (int i = 0; i < HH; i++) {
        u64 hi = hd[i];
        const ulonglong2* wr = (const ulonglong2*)(cW.m1w1 + (i + 1) * 32);
        #pragma unroll
        for (int j = 0; j < 8; j++) {
            ulonglong2 w = wr[j];
            a2[2*j]   = ffma2(hi, w.x, a2[2*j]);
            a2[2*j+1] = ffma2(hi, w.y, a2[2*j+1]);
        }
    }
    float a[32];
    #pragma unroll
    for (int j = 0; j < 16; j++) {
        u64 r = relu2(a2[j]);
        upk2(r, a[2*j], a[2*j+1]);
    }

    u64 b2[16];
    {
        const ulonglong2* bv = (const ulonglong2*)cW.m1b2;
        #pragma unroll
        for (int j = 0; j < 8; j++) { ulonglong2 b = bv[j]; b2[2*j] = b.x; b2[2*j+1] = b.y; }
    }
    #pragma unroll
    for (int i = 0; i < 32; i++) {
        u64 ai = dup2(a[i]);
        const ulonglong2* wr = (const ulonglong2*)(cW.m1w2 + i * 32);
        #pragma unroll
        for (int j = 0; j < 8; j++) {
            ulonglong2 w = wr[j];
            b2[2*j]   = ffma2(ai, w.x, b2[2*j]);
            b2[2*j+1] = ffma2(ai, w.y, b2[2*j+1]);
        }
    }
    u64 z2 = 0ULL;
    {
        const ulonglong2* wv = (const ulonglong2*)cW.m1w3;
        #pragma unroll
        for (int j = 0; j < 8; j++) {
            ulonglong2 w = wv[j];
            z2 = ffma2(relu2(b2[2*j]),   w.x, z2);
            z2 = ffma2(relu2(b2[2*j+1]), w.y, z2);
        }
    }
    float zl, zh; upk2(z2, zl, zh);
    return fast_sigmoid(zl + zh + cW.m1b3);
}

// Update MLP [x1,h(8),agg](10) -> 32 -> relu -> 8 -> relu -> tanh
__device__ __forceinline__ void mlp2(const u64 in2[10], float hnew[HH]) {
    u64 a2[16];
    {
        const ulonglong2* bv = (const ulonglong2*)cW.m2b1;
        #pragma unroll
        for (int j = 0; j < 8; j++) { ulonglong2 b = bv[j]; a2[2*j] = b.x; a2[2*j+1] = b.y; }
    }
    #pragma unroll
    for (int i = 0; i < 10; i++) {
        u64 vi = in2[i];
        const ulonglong2* wr = (const ulonglong2*)(cW.m2w1 + i * 32);
        #pragma unroll
        for (int j = 0; j < 8; j++) {
            ulonglong2 w = wr[j];
            a2[2*j]   = ffma2(vi, w.x, a2[2*j]);
            a2[2*j+1] = ffma2(vi, w.y, a2[2*j+1]);
        }
    }
    float a[32];
    #pragma unroll
    for (int j = 0; j < 16; j++) {
        u64 r = relu2(a2[j]);
        upk2(r, a[2*j], a[2*j+1]);
    }

    u64 b8[4];
    {
        const ulonglong2* bv = (const ulonglong2*)cW.m2b2;
        ulonglong2 b0 = bv[0], b1 = bv[1];
        b8[0] = b0.x; b8[1] = b0.y; b8[2] = b1.x; b8[3] = b1.y;
    }
    #pragma unroll
    for (int i = 0; i < 32; i++) {
        u64 ai = dup2(a[i]);
        const ulonglong2* wr = (const ulonglong2*)(cW.m2w2 + i * 8);
        ulonglong2 w0 = wr[0], w1 = wr[1];
        b8[0] = ffma2(ai, w0.x, b8[0]); b8[1] = ffma2(ai, w0.y, b8[1]);
        b8[2] = ffma2(ai, w1.x, b8[2]); b8[3] = ffma2(ai, w1.y, b8[3]);
    }
    // hidden_new = tanh(relu(z2))
    #pragma unroll
    for (int k = 0; k < 4; k++) {
        float lo, hi; upk2(relu2(b8[k]), lo, hi);
        hnew[2*k]   = fast_tanh_nonneg(lo);
        hnew[2*k+1] = fast_tanh_nonneg(hi);
    }
}

// Readout hidden(8) -> 16 -> relu -> 1 -> sigmoid (takes pre-dup'd hidden)
__device__ __forceinline__ float node_out(const u64 hd[HH]) {
    u64 o2[8];
    {
        const ulonglong2* bv = (const ulonglong2*)cW.ob1;
        #pragma unroll
        for (int m = 0; m < 4; m++) { ulonglong2 b = bv[m]; o2[2*m] = b.x; o2[2*m+1] = b.y; }
    }
    #pragma unroll
    for (int i = 0; i < HH; i++) {
        u64 hi = hd[i];
        const ulonglong2* wr = (const ulonglong2*)(cW.ow1 + i * 16);
        #pragma unroll
        for (int m = 0; m < 4; m++) {
            ulonglong2 w = wr[m];
            o2[2*m]   = ffma2(hi, w.x, o2[2*m]);
            o2[2*m+1] = ffma2(hi, w.y, o2[2*m+1]);
        }
    }
    u64 z2 = 0ULL;
    {
        const ulonglong2* wv = (const ulonglong2*)cW.ow2;
        #pragma unroll
        for (int m = 0; m < 4; m++) {
            ulonglong2 w = wv[m];
            z2 = ffma2(relu2(o2[2*m]),   w.x, z2);
            z2 = ffma2(relu2(o2[2*m+1]), w.y, z2);
        }
    }
    float zl, zh; upk2(z2, zl, zh);
    return fast_sigmoid(zl + zh + cW.ob2);
}

// ---------------- kernels ----------------

// One-time transposes, fused: edge_attr [E,T,1]->[T,E] and x [N,T,2]->[T,N]x2.
__global__ void transpose_kernel(const float* __restrict__ ea,
                                 const float* __restrict__ x) {
    int e = blockIdx.x * blockDim.x + threadIdx.x;
    if (e < EE) {
        #pragma unroll
        for (int t = 0; t < TT; t++) g_eaT[t * EE + e] = ea[e * TT + t];
    }
    if (e < NN) {
        #pragma unroll
        for (int t = 0; t < TT; t++) {
            float2 v = ((const float2*)x)[e * TT + t];
            g_x0T[t * NN + e] = v.x;
            g_x1T[t * NN + e] = v.y;
        }
    }
}

// Frame 0 prologue: hidden = 0, agg = 0, s = sigmoid(MLP1([x0, 0]))
__global__ void __launch_bounds__(128) prologue_kernel() {
    int n = blockIdx.x * blockDim.x + threadIdx.x;
    if (n >= NN) return;
    u64 hd[HH] = {0ULL,0ULL,0ULL,0ULL,0ULL,0ULL,0ULL,0ULL};
    u64 x0d = dup2(g_x0T[n]);
    g_s[n] = mlp1(x0d, hd);
    g_agg[n] = 0.0f;
    float4 z4 = make_float4(0.f, 0.f, 0.f, 0.f);
    ((float4*)g_hidden)[n * 2 + 0] = z4;
    ((float4*)g_hidden)[n * 2 + 1] = z4;
}

// Per-frame edge scatter: agg[dst] += s[src] * ea ; 8 edges per thread.
// Front-batched independent LDG.128s -> gathers -> atomics for deep MLP.
__global__ void edge_kernel(const int* __restrict__ ei, int t) {
    int e8 = blockIdx.x * blockDim.x + threadIdx.x;
    if (e8 >= EE / 8) return;
    const int4*   sp = (const int4*)(ei + t * EE) + e8 * 2;
    const int4*   dp = (const int4*)(ei + (TT + t) * EE) + e8 * 2;
    const float4* ap = (const float4*)(g_eaT + t * EE) + e8 * 2;
    int4 s0 = sp[0], s1 = sp[1];
    int4 d0 = dp[0], d1 = dp[1];
    float4 a0 = ap[0], a1 = ap[1];
    float m0 = __ldg(&g_s[s0.x]) * a0.x;
    float m1 = __ldg(&g_s[s0.y]) * a0.y;
    float m2 = __ldg(&g_s[s0.z]) * a0.z;
    float m3 = __ldg(&g_s[s0.w]) * a0.w;
    float m4 = __ldg(&g_s[s1.x]) * a1.x;
    float m5 = __ldg(&g_s[s1.y]) * a1.y;
    float m6 = __ldg(&g_s[s1.z]) * a1.z;
    float m7 = __ldg(&g_s[s1.w]) * a1.w;
    atomicAdd(&g_agg[d0.x], m0);
    atomicAdd(&g_agg[d0.y], m1);
    atomicAdd(&g_agg[d0.z], m2);
    atomicAdd(&g_agg[d0.w], m3);
    atomicAdd(&g_agg[d1.x], m4);
    atomicAdd(&g_agg[d1.y], m5);
    atomicAdd(&g_agg[d1.z], m6);
    atomicAdd(&g_agg[d1.w], m7);
}

// Per-frame node update (+ fused message-MLP for next frame), 1 node/lane.
__global__ void __launch_bounds__(128) update_kernel(float* __restrict__ out, int t) {
    int n = blockIdx.x * blockDim.x + threadIdx.x;
    if (n >= NN) return;

    float4 h0 = ((const float4*)g_hidden)[n * 2 + 0];
    float4 h1 = ((const float4*)g_hidden)[n * 2 + 1];

    u64 in2[10];
    in2[0] = dup2(g_x1T[t * NN + n]);
    in2[1] = dup2(h0.x); in2[2] = dup2(h0.y); in2[3] = dup2(h0.z); in2[4] = dup2(h0.w);
    in2[5] = dup2(h1.x); in2[6] = dup2(h1.y); in2[7] = dup2(h1.z); in2[8] = dup2(h1.w);
    in2[9] = dup2(g_agg[n]);   // AGG_MEAN=0, AGG_VAR=1 -> identity norm

    float hn[HH];
    mlp2(in2, hn);

    ((float4*)g_hidden)[n * 2 + 0] = make_float4(hn[0], hn[1], hn[2], hn[3]);
    ((float4*)g_hidden)[n * 2 + 1] = make_float4(hn[4], hn[5], hn[6], hn[7]);

    u64 hd[HH];
    #pragma unroll
    for (int i = 0; i < HH; i++) hd[i] = dup2(hn[i]);

    out[t * NN + n] = node_out(hd);

    if (t < TT - 1) {
        u64 x0d = dup2(g_x0T[(t + 1) * NN + n]);
        g_s[n] = mlp1(x0d, hd);
        g_agg[n] = 0.0f;
    }
}

// ---------------- launch ----------------
extern "C" void kernel_launch(void* const* d_in, const int* in_sizes, int n_in,
                              void* d_out, int out_size) {
    const float* x  = (const float*)d_in[0];
    const int*   ei = (const int*)d_in[1];
    const float* ea = (const float*)d_in[2];
    WPtrs p;
    p.m1w1 = (const float*)d_in[3];  p.m1b1 = (const float*)d_in[4];
    p.m1w2 = (const float*)d_in[5];  p.m1b2 = (const float*)d_in[6];
    p.m1w3 = (const float*)d_in[7];  p.m1b3 = (const float*)d_in[8];
    p.m2w1 = (const float*)d_in[9];  p.m2b1 = (const float*)d_in[10];
    p.m2w2 = (const float*)d_in[11]; p.m2b2 = (const float*)d_in[12];
    p.ow1  = (const float*)d_in[13]; p.ob1  = (const float*)d_in[14];
    p.ow2  = (const float*)d_in[15]; p.ob2  = (const float*)d_in[16];
    float* out = (float*)d_out;

    // Stage weights in device memory, then copy into the constant bank.
    pack_weights_kernel<<<1, 256>>>(p);
    void* cw_addr = nullptr;
    void* st_addr = nullptr;
    cudaGetSymbolAddress(&cw_addr, cW);
    cudaGetSymbolAddress(&st_addr, g_wstage);
    cudaMemcpyAsync(cw_addr, st_addr, sizeof(Weights), cudaMemcpyDeviceToDevice, 0);

    transpose_kernel<<<(EE + 255) / 256, 256>>>(ea, x);
    prologue_kernel<<<(NN + 127) / 128, 128>>>();
    for (int t = 0; t < TT; t++) {
        edge_kernel<<<(EE / 8 + 255) / 256, 256>>>(ei, t);
        update_kernel<<<(NN + 127) / 128, 128>>>(out, t);
    }
}